// round 17
// baseline (speedup 1.0000x reference)
#include <cuda_runtime.h>
#include <cuda_bf16.h>
#include <math.h>
#include <stdint.h>

// ---------------- problem constants ----------------
#define K_   256
#define KP1  257
#define D_   256
#define V_   50000
#define T_   512
#define B_   256
#define MD   512              // M*D
#define R2   66049            // KP1*KP1
#define EPS  1e-5f
#define NQ   (T_ * B_)        // 131072 queries

#define NRT  517              // ceil(R2/128)
#define NVT  391              // ceil(V/128)
#define NBTR 259              // ceil(R2/256)
#define NBEM 196              // ceil(V/256)
#define NQOFF (NBTR + NBEM)   // 455

// ---------------- scratch ----------------
__device__ __nv_bfloat16 g_h_bf[K_ * D_];
__device__ float g_lse_em[K_];
__device__ float g_part_em[NVT * K_];
__device__ __nv_bfloat16 g_At_bf[KP1 * MD];   // includes tm_bias (folded at t_pre)
__device__ __nv_bfloat16 g_Bt_bf[KP1 * MD];
// bf16 weights
__device__ __nv_bfloat16 g_lembs_bf[K_ * D_];
__device__ __nv_bfloat16 g_emW_bf[D_ * D_];
__device__ __nv_bfloat16 g_tlembs_bf[KP1 * D_];
__device__ __nv_bfloat16 g_tmW_bf[MD * MD];
__device__ __nv_bfloat16 g_tdW_bf[K_ * MD];
__device__ __nv_bfloat16 g_decW_bf[(size_t)V_ * D_];
// query machinery (zero at process start; every kernel_launch call restores
// the zeroed state before exit -> deterministic across graph replays)
__device__ int g_cnt_tr[R2];
__device__ int g_cur_tr[R2];
__device__ int g_qbeg_tr[R2];
__device__ int g_qend_tr[R2];
__device__ int g_cnt_em[V_];
__device__ int g_cur_em[V_];
__device__ int g_qbeg_em[V_];
__device__ int g_qend_em[V_];
__device__ int g_qcursor[2];
__device__ uint32_t g_qdat_tr[NQ];
__device__ uint32_t g_qdat_em[NQ];
__device__ float g_q_tr[NQ];
__device__ float g_q_em[NQ];

// ================= helpers =================
__device__ __forceinline__ uint32_t s2u(const void* p) {
    uint32_t a;
    asm("{ .reg .u64 t; cvta.to.shared.u64 t, %1; cvt.u32.u64 %0, t; }" : "=r"(a) : "l"(p));
    return a;
}
__device__ __forceinline__ uint32_t pack_bf2(float a, float b) {
    uint32_t u;
    asm("cvt.rn.bf16x2.f32 %0, %1, %2;" : "=r"(u) : "f"(b), "f"(a));
    return u;
}
__device__ __forceinline__ float2 bf2f(uint32_t u) {
    return __bfloat1622float2(*reinterpret_cast<const __nv_bfloat162*>(&u));
}
__device__ __forceinline__ void cp16(uint32_t dst, const void* src, bool ok) {
    int sz = ok ? 16 : 0;
    asm volatile("cp.async.cg.shared.global [%0], [%1], 16, %2;"
                 :: "r"(dst), "l"(src), "r"(sz) : "memory");
}
#define CP_COMMIT() asm volatile("cp.async.commit_group;" ::: "memory")
template<int N>
__device__ __forceinline__ void cp_wait() {
    asm volatile("cp.async.wait_group %0;" :: "n"(N) : "memory");
}

#define LDSM4(r, addr) \
    asm volatile("ldmatrix.sync.aligned.m8n8.x4.shared.b16 {%0,%1,%2,%3}, [%4];" \
                 : "=r"((r)[0]), "=r"((r)[1]), "=r"((r)[2]), "=r"((r)[3]) : "r"(addr))

#define MMA16816(c, a, b0v, b1v) \
    asm volatile("mma.sync.aligned.m16n8k16.row.col.f32.bf16.bf16.f32 " \
                 "{%0,%1,%2,%3}, {%4,%5,%6,%7}, {%8,%9}, {%0,%1,%2,%3};" \
                 : "+f"((c)[0]), "+f"((c)[1]), "+f"((c)[2]), "+f"((c)[3]) \
                 : "r"((a)[0]), "r"((a)[1]), "r"((a)[2]), "r"((a)[3]), "r"(b0v), "r"(b1v))

// generic pipeline stage layout: A 128x80 + B 256x80 = 30720 per stage
#define ASZ    10240
#define STAGE  30720
#define SMEMSZ (2 * STAGE)                  // k_mlp_pre (2-stage)
#define EM_LOG  (3 * STAGE)                 // em body: 3 stages then logits tile
#define EM_SMEM (EM_LOG + 133120)           // 225280
// tr body: resident A 128x1040 = 133120; 4 B stages of 20480; lse; rps
#define TRF_B    133120
#define TRF_BST  20480
#define TRF_LSE  215040
#define TRF_RPS  215552
#define TRF_SMEM 216576
#define BIG_SMEM 225280                     // max(TRF_SMEM, EM_SMEM)

// ---------------- generic HMMA pipeline (A+B staged, NS stages) ----------------
template<int NS>
__device__ __forceinline__ void mma_pipeline(
    const __nv_bfloat16* __restrict__ Aptr, int lda, int AM,
    const __nv_bfloat16* __restrict__ Bptr, int ldb,
    int NC, int m0, uint32_t sbase, float acc[16][4])
{
    const int tid = threadIdx.x;
    const int lane = tid & 31, wid = tid >> 5;
    const int wm = wid & 7, wn = wid >> 3;

    const int arow = tid >> 2, aq = tid & 3;
    const int gmA = m0 + arow;
    const bool aok = gmA < AM;
    const __nv_bfloat16* asrc = Aptr + (size_t)(aok ? gmA : 0) * lda + aq * 8;
    const __nv_bfloat16* bsrc1 = Bptr + (size_t)arow * ldb + aq * 8;
    const __nv_bfloat16* bsrc2 = Bptr + (size_t)(128 + arow) * ldb + aq * 8;
    const uint32_t adst  = sbase + arow * 80 + aq * 16;
    const uint32_t bdst1 = sbase + ASZ + arow * 80 + aq * 16;
    const uint32_t bdst2 = sbase + ASZ + (128 + arow) * 80 + aq * 16;

    const uint32_t afrag = sbase + (wm * 16 + (lane & 15)) * 80 + (lane >> 4) * 16;
    const uint32_t bfrag = sbase + ASZ + (wn * 128 + (lane & 7)) * 80 + (lane >> 3) * 16;

#pragma unroll
    for (int pc = 0; pc < NS - 1; pc++) {
        if (pc < NC) {
            const uint32_t so = pc * STAGE;
            const int koff = pc * 32;
            cp16(adst + so, asrc + koff, aok);
            cp16(bdst1 + so, bsrc1 + koff, true);
            cp16(bdst2 + so, bsrc2 + koff, true);
        }
        CP_COMMIT();
    }

#pragma unroll 1
    for (int c = 0; c < NC; c++) {
        if (c + NS - 1 < NC) {
            const uint32_t nso = ((c + NS - 1) % NS) * STAGE;
            const int koff = (c + NS - 1) * 32;
            cp16(adst + nso, asrc + koff, aok);
            cp16(bdst1 + nso, bsrc1 + koff, true);
            cp16(bdst2 + nso, bsrc2 + koff, true);
            CP_COMMIT();
            cp_wait<NS - 1>();
        } else {
            cp_wait<0>();
        }
        __syncthreads();
        const uint32_t so = (c % NS) * STAGE;
        uint32_t a0[4], a1[4];
        LDSM4(a0, afrag + so);
        LDSM4(a1, afrag + so + 32);
        const uint32_t bb = bfrag + so;
#pragma unroll
        for (int ntl = 0; ntl < 16; ntl++) {
            uint32_t bq[4];
            LDSM4(bq, bb + ntl * 640);
            MMA16816(acc[ntl], a0, bq[0], bq[1]);
            MMA16816(acc[ntl], a1, bq[2], bq[3]);
        }
        __syncthreads();
    }
}

// ---------------- launch 1: query count (+ qcursor reset) ----------------
__global__ __launch_bounds__(256) void k_qcount(const int* __restrict__ x,
                                                const int* __restrict__ z)
{
    if (blockIdx.x == 0 && threadIdx.x < 2) g_qcursor[threadIdx.x] = 0;
    int idx = blockIdx.x * 256 + threadIdx.x;
    int t = idx >> 8;
    int zp1 = (t >= 1) ? z[idx - B_] : K_;
    int zp2 = (t >= 2) ? z[idx - 2 * B_] : K_;
    atomicAdd(&g_cnt_tr[zp2 * KP1 + zp1], 1);
    atomicAdd(&g_cnt_em[x[idx]], 1);
}

// ---------------- launch 2: conversions + query offsets (merged) ----------------
__device__ __forceinline__ void cvt4(const float* __restrict__ s,
                                     __nv_bfloat16* __restrict__ d, size_t i)
{
    float4 f = *(const float4*)(s + i * 4);
    uint2 u; u.x = pack_bf2(f.x, f.y); u.y = pack_bf2(f.z, f.w);
    *(uint2*)(d + i * 4) = u;
}

__global__ __launch_bounds__(256) void k_cvt_offs(
    const float* __restrict__ lembs, const float* __restrict__ emW,
    const float* __restrict__ tlembs, const float* __restrict__ tmW,
    const float* __restrict__ tdW, const float* __restrict__ decW)
{
    const int tid = threadIdx.x;
    if (blockIdx.x < NQOFF) {
        // qoffs body: parallel offsets via atomic range allocation.
        // Any disjoint allocation is correct: scatter writes land at
        // g_q_*[qid], so bucket placement never affects output.
        // Also restores cnt/cur to zero for the next kernel_launch call.
        const bool em = blockIdx.x >= NBTR;
        const int blk = em ? blockIdx.x - NBTR : blockIdx.x;
        const int n = em ? V_ : R2;
        int* cnt = em ? g_cnt_em : g_cnt_tr;
        int* cur = em ? g_cur_em : g_cur_tr;
        int* qbeg = em ? g_qbeg_em : g_qbeg_tr;
        int* qend = em ? g_qend_em : g_qend_tr;

        const int i = blk * 256 + tid;
        const int v = (i < n) ? cnt[i] : 0;
        if (i < n) { cnt[i] = 0; cur[i] = 0; }
        __shared__ int sh[256];
        __shared__ int base;
        sh[tid] = v;
        __syncthreads();
#pragma unroll
        for (int o = 1; o < 256; o <<= 1) {
            int t = (tid >= o) ? sh[tid - o] : 0;
            __syncthreads();
            sh[tid] += t;
            __syncthreads();
        }
        int incl = sh[tid];
        if (tid == 255) base = atomicAdd(&g_qcursor[em ? 1 : 0], incl);
        __syncthreads();
        if (i < n) {
            qbeg[i] = base + incl - v;
            qend[i] = base + incl;
        }
    } else {
        const int i0 = (blockIdx.x - NQOFF) * 256 + tid;
        const int gs = (gridDim.x - NQOFF) * 256;
        for (int i = i0; i < K_ * D_ / 4; i += gs)  cvt4(lembs, g_lembs_bf, i);
        for (int i = i0; i < D_ * D_ / 4; i += gs)  cvt4(emW, g_emW_bf, i);
        for (int i = i0; i < KP1 * D_ / 4; i += gs) cvt4(tlembs, g_tlembs_bf, i);
        for (int i = i0; i < MD * MD / 4; i += gs)  cvt4(tmW, g_tmW_bf, i);
        for (int i = i0; i < K_ * MD / 4; i += gs)  cvt4(tdW, g_tdW_bf, i);
        for (int i = i0; i < V_ * D_ / 4; i += gs)  cvt4(decW, g_decW_bf, i);
    }
}

// ================= launch 3 bodies: MLPs + qfill =================
__device__ void em_mlp_body(
    char* smc, uint32_t sbase, int bx,
    const float* __restrict__ lembs, const float* __restrict__ em_bias,
    const float* __restrict__ em_g, const float* __restrict__ em_beta)
{
    const int tid = threadIdx.x;
    const int lane = tid & 31, wid = tid >> 5;
    const int wm = wid & 7, wn = wid >> 3;
    const int m0 = bx * 128;

    float acc[16][4];
#pragma unroll
    for (int i = 0; i < 16; i++)
#pragma unroll
        for (int j = 0; j < 4; j++) acc[i][j] = 0.f;

    mma_pipeline<2>(g_lembs_bf, D_, K_, g_emW_bf, D_, D_ / 32, m0, sbase, acc);

    const int r1 = wm * 16 + (lane >> 2);
    const int r2 = r1 + 8;
    const int gm1 = m0 + r1, gm2 = m0 + r2;
    float s1 = 0.f, q1 = 0.f, s2 = 0.f, q2 = 0.f;
#pragma unroll
    for (int ntl = 0; ntl < 16; ntl++) {
        int cb = wn * 128 + ntl * 8 + 2 * (lane & 3);
        float2 b2v = *(const float2*)(em_bias + cb);
        float2 l1 = *(const float2*)(lembs + gm1 * D_ + cb);
        float2 l2 = *(const float2*)(lembs + gm2 * D_ + cb);
        float v0 = l1.x + fmaxf(acc[ntl][0] + b2v.x, 0.f);
        float v1 = l1.y + fmaxf(acc[ntl][1] + b2v.y, 0.f);
        float v2 = l2.x + fmaxf(acc[ntl][2] + b2v.x, 0.f);
        float v3 = l2.y + fmaxf(acc[ntl][3] + b2v.y, 0.f);
        acc[ntl][0] = v0; acc[ntl][1] = v1; acc[ntl][2] = v2; acc[ntl][3] = v3;
        s1 += v0 + v1; q1 += v0 * v0 + v1 * v1;
        s2 += v2 + v3; q2 += v2 * v2 + v3 * v3;
    }
#pragma unroll
    for (int o = 1; o < 4; o <<= 1) {
        s1 += __shfl_xor_sync(0xffffffffu, s1, o); q1 += __shfl_xor_sync(0xffffffffu, q1, o);
        s2 += __shfl_xor_sync(0xffffffffu, s2, o); q2 += __shfl_xor_sync(0xffffffffu, q2, o);
    }
    float* sS = (float*)smc;
    float* sQ = (float*)smc + 256;
    if ((lane & 3) == 0) {
        sS[r1 * 2 + wn] = s1; sQ[r1 * 2 + wn] = q1;
        sS[r2 * 2 + wn] = s2; sQ[r2 * 2 + wn] = q2;
    }
    __syncthreads();
    float mu1 = (sS[r1 * 2] + sS[r1 * 2 + 1]) * (1.f / D_);
    float rs1 = rsqrtf((sQ[r1 * 2] + sQ[r1 * 2 + 1]) * (1.f / D_) - mu1 * mu1 + EPS);
    float mu2 = (sS[r2 * 2] + sS[r2 * 2 + 1]) * (1.f / D_);
    float rs2 = rsqrtf((sQ[r2 * 2] + sQ[r2 * 2 + 1]) * (1.f / D_) - mu2 * mu2 + EPS);
#pragma unroll
    for (int ntl = 0; ntl < 16; ntl++) {
        int cb = wn * 128 + ntl * 8 + 2 * (lane & 3);
        float2 gg = *(const float2*)(em_g + cb);
        float2 bt = *(const float2*)(em_beta + cb);
        float h0 = (acc[ntl][0] - mu1) * rs1 * gg.x + bt.x;
        float h1 = (acc[ntl][1] - mu1) * rs1 * gg.y + bt.y;
        float h2 = (acc[ntl][2] - mu2) * rs2 * gg.x + bt.x;
        float h3 = (acc[ntl][3] - mu2) * rs2 * gg.y + bt.y;
        *(uint32_t*)(g_h_bf + gm1 * D_ + cb) = pack_bf2(h0, h1);
        *(uint32_t*)(g_h_bf + gm2 * D_ + cb) = pack_bf2(h2, h3);
    }
}

// t_pre: writes At (+tm_bias folded) / Bt in bf16
__device__ void t_pre_body(uint32_t sbase, int bx, int by,
                           const float* __restrict__ tm_bias)
{
    const int tid = threadIdx.x;
    const int lane = tid & 31, wid = tid >> 5;
    const int wm = wid & 7, wn = wid >> 3;
    const int m0 = bx * 128;
    const int n0 = (by & 1) * 256;
    const int half = by >> 1;
    const int bcol0 = half * 256;

    float acc[16][4];
#pragma unroll
    for (int i = 0; i < 16; i++)
#pragma unroll
        for (int j = 0; j < 4; j++) acc[i][j] = 0.f;

    mma_pipeline<2>(g_tlembs_bf, D_, KP1,
                    g_tmW_bf + (size_t)n0 * MD + bcol0, MD, 256 / 32, m0, sbase, acc);

    __nv_bfloat16* out = half ? g_Bt_bf : g_At_bf;
    const int r1 = wm * 16 + (lane >> 2);
    const int gm1 = m0 + r1, gm2 = gm1 + 8;
#pragma unroll
    for (int ntl = 0; ntl < 16; ntl++) {
        int cb = n0 + wn * 128 + ntl * 8 + 2 * (lane & 3);
        float bx0 = 0.f, bx1 = 0.f;
        if (half == 0) {           // fold tm_bias into At
            float2 bb = *(const float2*)(tm_bias + cb);
            bx0 = bb.x; bx1 = bb.y;
        }
        if (gm1 < KP1) *(uint32_t*)(out + gm1 * MD + cb) =
            pack_bf2(acc[ntl][0] + bx0, acc[ntl][1] + bx1);
        if (gm2 < KP1) *(uint32_t*)(out + gm2 * MD + cb) =
            pack_bf2(acc[ntl][2] + bx0, acc[ntl][3] + bx1);
    }
}

__device__ void qfill_body(int qblk, const int* __restrict__ x,
                           const int* __restrict__ z)
{
    int idx = qblk * 512 + threadIdx.x;
    int t = idx >> 8;
    int zt = z[idx];
    int zp1 = (t >= 1) ? z[idx - B_] : K_;
    int zp2 = (t >= 2) ? z[idx - 2 * B_] : K_;
    int lin = zp2 * KP1 + zp1;
    uint32_t pk = (uint32_t)idx | ((uint32_t)zt << 17);
    int pos = g_qbeg_tr[lin] + atomicAdd(&g_cur_tr[lin], 1);
    g_qdat_tr[pos] = pk;
    int xt = x[idx];
    pos = g_qbeg_em[xt] + atomicAdd(&g_cur_em[xt], 1);
    g_qdat_em[pos] = pk;
}

// launch 3: blocks 0-1 em_mlp, 2-13 t_pre, 14..269 qfill
__global__ __launch_bounds__(512) void k_mlp_pre(
    const float* __restrict__ lembs, const float* __restrict__ em_bias,
    const float* __restrict__ em_g, const float* __restrict__ em_beta,
    const float* __restrict__ tm_bias,
    const int* __restrict__ x, const int* __restrict__ z)
{
    extern __shared__ char smc[];
    const uint32_t sbase = s2u(smc);
    if (blockIdx.x < 2)
        em_mlp_body(smc, sbase, blockIdx.x, lembs, em_bias, em_g, em_beta);
    else if (blockIdx.x < 14) {
        int b = blockIdx.x - 2;
        t_pre_body(sbase, b % 3, b / 3, tm_bias);
    } else {
        qfill_body(blockIdx.x - 14, x, z);
    }
}

// ================= launch 4 bodies: big fused kernel =================
__device__ void tr_body(
    char* smc, uint32_t sbase, int bx,
    const float* __restrict__ tlembs,
    const float* __restrict__ tn_g, const float* __restrict__ tn_beta,
    const float* __restrict__ tdb)
{
    const int tid = threadIdx.x;
    const int lane = tid & 31, wid = tid >> 5;
    const int wm = wid & 7, wn = wid >> 3;
    const int m0 = bx * 128;

    // prefetch B chunks 0..2 into stages 0..2
    {
        const int row1 = tid >> 2, q1 = (tid & 3);
        const int row2 = (tid + 512) >> 2, q2 = (tid & 3);
#pragma unroll
        for (int pc = 0; pc < 3; pc++) {
            cp16(sbase + TRF_B + pc * TRF_BST + row1 * 80 + q1 * 16,
                 g_tdW_bf + (size_t)row1 * MD + pc * 32 + q1 * 8, true);
            cp16(sbase + TRF_B + pc * TRF_BST + row2 * 80 + q2 * 16,
                 g_tdW_bf + (size_t)row2 * MD + pc * 32 + q2 * 8, true);
            CP_COMMIT();
        }
    }

    // ---- phase 1: build th tile (128 rows x 512 bf16) resident in smem ----
    // At (bf16) already contains tm_bias; Bt bf16.
#pragma unroll 1
    for (int k8 = 0; k8 < 8; k8++) {
        int rr = wid * 8 + k8;
        int gm = m0 + rr;
        char* rbase = smc + rr * 1040;
        if (gm < R2) {
            int i = gm / KP1, j = gm - i * KP1;
            float v[16];
            float s = 0.f, q = 0.f;
#pragma unroll
            for (int qq = 0; qq < 2; qq++) {
                int e = 8 * lane + 256 * qq;
                const float* crow = tlembs + (qq ? j : i) * D_ + 8 * lane;
                float4 c0 = *(const float4*)crow;
                float4 c1 = *(const float4*)(crow + 4);
                uint4 au = *(const uint4*)(g_At_bf + i * MD + e);
                uint4 bu = *(const uint4*)(g_Bt_bf + j * MD + e);
                float2 a0 = bf2f(au.x), a1 = bf2f(au.y), a2 = bf2f(au.z), a3 = bf2f(au.w);
                float2 b0 = bf2f(bu.x), b1 = bf2f(bu.y), b2 = bf2f(bu.z), b3 = bf2f(bu.w);
                float* vp = v + qq * 8;
                vp[0] = c0.x + fmaxf(a0.x + b0.x, 0.f);
                vp[1] = c0.y + fmaxf(a0.y + b0.y, 0.f);
                vp[2] = c0.z + fmaxf(a1.x + b1.x, 0.f);
                vp[3] = c0.w + fmaxf(a1.y + b1.y, 0.f);
                vp[4] = c1.x + fmaxf(a2.x + b2.x, 0.f);
                vp[5] = c1.y + fmaxf(a2.y + b2.y, 0.f);
                vp[6] = c1.z + fmaxf(a3.x + b3.x, 0.f);
                vp[7] = c1.w + fmaxf(a3.y + b3.y, 0.f);
#pragma unroll
                for (int k = 0; k < 8; k++) { s += vp[k]; q += vp[k] * vp[k]; }
            }
#pragma unroll
            for (int o = 16; o; o >>= 1) {
                s += __shfl_xor_sync(0xffffffffu, s, o);
                q += __shfl_xor_sync(0xffffffffu, q, o);
            }
            float mu = s * (1.f / MD);
            float rstd = rsqrtf(q * (1.f / MD) - mu * mu + EPS);
#pragma unroll
            for (int qq = 0; qq < 2; qq++) {
                int e = 8 * lane + 256 * qq;
                float4 g0 = *(const float4*)(tn_g + e);
                float4 g1 = *(const float4*)(tn_g + e + 4);
                float4 t0 = *(const float4*)(tn_beta + e);
                float4 t1 = *(const float4*)(tn_beta + e + 4);
                const float* vp = v + qq * 8;
                uint4 u;
                u.x = pack_bf2((vp[0] - mu) * rstd * g0.x + t0.x,
                               (vp[1] - mu) * rstd * g0.y + t0.y);
                u.y = pack_bf2((vp[2] - mu) * rstd * g0.z + t0.z,
                               (vp[3] - mu) * rstd * g0.w + t0.w);
                u.z = pack_bf2((vp[4] - mu) * rstd * g1.x + t1.x,
                               (vp[5] - mu) * rstd * g1.y + t1.y);
                u.w = pack_bf2((vp[6] - mu) * rstd * g1.z + t1.z,
                               (vp[7] - mu) * rstd * g1.w + t1.w);
                *(uint4*)(rbase + 16 * lane + 512 * qq) = u;
            }
        } else {
#pragma unroll
            for (int qq = 0; qq < 2; qq++)
                *(uint4*)(rbase + 16 * lane + 512 * qq) = make_uint4(0, 0, 0, 0);
        }
    }
    __syncthreads();

    // ---- phase 2: MMA, A resident, B 4-stage ----
    float acc[16][4];
#pragma unroll
    for (int i = 0; i < 16; i++)
#pragma unroll
        for (int j = 0; j < 4; j++) acc[i][j] = 0.f;

    const uint32_t afrag = sbase + (wm * 16 + (lane & 15)) * 1040 + (lane >> 4) * 16;
    const uint32_t bfragbase = (wn * 128 + (lane & 7)) * 80 + (lane >> 3) * 16;
    const int prow1 = tid >> 2, prow2 = (tid + 512) >> 2, pq = tid & 3;

#pragma unroll 1
    for (int c = 0; c < 16; c++) {
        if (c + 3 < 16) {
            const uint32_t bso = ((c + 3) & 3) * TRF_BST;
            cp16(sbase + TRF_B + bso + prow1 * 80 + pq * 16,
                 g_tdW_bf + (size_t)prow1 * MD + (c + 3) * 32 + pq * 8, true);
            cp16(sbase + TRF_B + bso + prow2 * 80 + pq * 16,
                 g_tdW_bf + (size_t)prow2 * MD + (c + 3) * 32 + pq * 8, true);
            CP_COMMIT();
            cp_wait<3>();
        } else if (c == 13) cp_wait<2>();
        else if (c == 14) cp_wait<1>();
        else cp_wait<0>();
        __syncthreads();
        uint32_t a0[4], a1[4];
        LDSM4(a0, afrag + c * 64);
        LDSM4(a1, afrag + c * 64 + 32);
        const uint32_t bb = sbase + TRF_B + (c & 3) * TRF_BST + bfragbase;
#pragma unroll
        for (int ntl = 0; ntl < 16; ntl++) {
            uint32_t bq[4];
            LDSM4(bq, bb + ntl * 640);
            MMA16816(acc[ntl], a0, bq[0], bq[1]);
            MMA16816(acc[ntl], a1, bq[2], bq[3]);
        }
        __syncthreads();
    }

    // ---- phase 3: logits to smem (over A region), row lse, query scatter ----
    const int lr1 = wm * 16 + (lane >> 2);
    const int lr2 = lr1 + 8;
    float e1 = 0.f, e2 = 0.f;
    const int colb = wn * 128 + 2 * (lane & 3);
#pragma unroll
    for (int ntl = 0; ntl < 16; ntl++) {
        int cb = colb + ntl * 8;
        float t0 = __ldg(&tdb[cb]), t1 = __ldg(&tdb[cb + 1]);
        float lg0 = acc[ntl][0] + t0, lg1 = acc[ntl][1] + t1;
        float lg2 = acc[ntl][2] + t0, lg3 = acc[ntl][3] + t1;
        *(float2*)(smc + lr1 * 1040 + 4 * cb) = make_float2(lg0, lg1);
        *(float2*)(smc + lr2 * 1040 + 4 * cb) = make_float2(lg2, lg3);
        e1 += __expf(lg0) + __expf(lg1);
        e2 += __expf(lg2) + __expf(lg3);
    }
#pragma unroll
    for (int o = 1; o < 4; o <<= 1) {
        e1 += __shfl_xor_sync(0xffffffffu, e1, o);
        e2 += __shfl_xor_sync(0xffffffffu, e2, o);
    }
    float* rps = (float*)(smc + TRF_RPS);
    if ((lane & 3) == 0) {
        rps[lr1 * 2 + wn] = e1;
        rps[lr2 * 2 + wn] = e2;
    }
    __syncthreads();
    float* lse = (float*)(smc + TRF_LSE);
    if (tid < 128) lse[tid] = __logf(rps[tid * 2] + rps[tid * 2 + 1]);
    __syncthreads();
    if (tid < 128) {
        int gm = m0 + tid;
        if (gm < R2) {
            int p0 = g_qbeg_tr[gm], p1 = g_qend_tr[gm];
            const float* lrow = (const float*)(smc + tid * 1040);
            float l = lse[tid];
            for (int p = p0; p < p1; p++) {
                uint32_t pk = g_qdat_tr[p];
                int qid = pk & 0x1FFFF;
                int zt = pk >> 17;
                g_q_tr[qid] = lrow[zt] - l;
            }
        }
    }
}

__device__ void em_body(char* smc, uint32_t sbase, int bx,
                        const float* __restrict__ decb)
{
    const int tid = threadIdx.x;
    const int lane = tid & 31, wid = tid >> 5;
    const int wm = wid & 7, wn = wid >> 3;
    const int m0 = bx * 128;

    float acc[16][4];
#pragma unroll
    for (int i = 0; i < 16; i++)
#pragma unroll
        for (int j = 0; j < 4; j++) acc[i][j] = 0.f;

    mma_pipeline<3>(g_decW_bf, D_, V_, g_h_bf, D_, D_ / 32, m0, sbase, acc);

    const int lr1 = wm * 16 + (lane >> 2);
    const int lr2 = lr1 + 8;
    const int gm1 = m0 + lr1, gm2 = m0 + lr2;
    const bool ok1 = gm1 < V_, ok2 = gm2 < V_;
    const float b1 = ok1 ? __ldg(&decb[gm1]) : 0.f;
    const float b2 = ok2 ? __ldg(&decb[gm2]) : 0.f;
    float* cps = (float*)smc;   // [256][8]
#pragma unroll
    for (int ntl = 0; ntl < 16; ntl++) {
        int c0 = wn * 128 + ntl * 8 + 2 * (lane & 3);
        float lg0 = acc[ntl][0] + b1, lg1 = acc[ntl][1] + b1;
        float lg2 = acc[ntl][2] + b2, lg3 = acc[ntl][3] + b2;
        *(float2*)(smc + EM_LOG + lr1 * 1040 + 4 * c0) = make_float2(lg0, lg1);
        *(float2*)(smc + EM_LOG + lr2 * 1040 + 4 * c0) = make_float2(lg2, lg3);
        float v0 = (ok1 ? __expf(lg0) : 0.f) + (ok2 ? __expf(lg2) : 0.f);
        float v1 = (ok1 ? __expf(lg1) : 0.f) + (ok2 ? __expf(lg3) : 0.f);
#pragma unroll
        for (int o = 4; o < 32; o <<= 1) {
            v0 += __shfl_xor_sync(0xffffffffu, v0, o);
            v1 += __shfl_xor_sync(0xffffffffu, v1, o);
        }
        if (lane < 4) {
            int cc = wn * 128 + ntl * 8 + 2 * lane;
            cps[cc * 8 + wm] = v0;
            cps[(cc + 1) * 8 + wm] = v1;
        }
    }
    __syncthreads();
    if (tid < 256) {
        float s = 0.f;
#pragma unroll
        for (int w = 0; w < 8; w++) s += cps[tid * 8 + w];
        g_part_em[bx * K_ + tid] = s;
    }
    if (tid < 128) {
        int gm = m0 + tid;
        if (gm < V_) {
            int p0 = g_qbeg_em[gm], p1 = g_qend_em[gm];
            const float* lrow = (const float*)(smc + EM_LOG + tid * 1040);
            for (int p = p0; p < p1; p++) {
                uint32_t pk = g_qdat_em[p];
                int qid = pk & 0x1FFFF;
                int zt = pk >> 17;
                g_q_em[qid] = lrow[zt];
            }
        }
    }
}

// launch 4: merged transition (blocks 0..516) + emission (blocks 517..907)
__global__ __launch_bounds__(512) void k_big(
    const float* __restrict__ tlembs,
    const float* __restrict__ tn_g, const float* __restrict__ tn_beta,
    const float* __restrict__ tdb, const float* __restrict__ decb)
{
    extern __shared__ char smc[];
    const uint32_t sbase = s2u(smc);
    if (blockIdx.x < NRT)
        tr_body(smc, sbase, blockIdx.x, tlembs, tn_g, tn_beta, tdb);
    else
        em_body(smc, sbase, blockIdx.x - NRT, decb);
}

// ---------------- launches 5-6: reductions ----------------
__global__ __launch_bounds__(128) void k_red_em()
{
    const int k = blockIdx.x;
    const int tid = threadIdx.x;
    __shared__ float red[128];
    float s = 0.f;
    for (int c = tid; c < NVT; c += 128) s += g_part_em[c * K_ + k];
    red[tid] = s;
    __syncthreads();
    for (int st = 64; st; st >>= 1) {
        if (tid < st) red[tid] += red[tid + st];
        __syncthreads();
    }
    if (tid == 0) g_lse_em[k] = __logf(red[0]);
}

__global__ __launch_bounds__(512) void k_final(const int* __restrict__ z,
                                               float* __restrict__ out)
{
    __shared__ float red[512];
    const int b = blockIdx.x;
    const int t = threadIdx.x;
    const int idx = t * B_ + b;
    int zt = z[idx];
    red[t] = g_q_em[idx] - g_lse_em[zt] + g_q_tr[idx];
    __syncthreads();
    for (int s = 256; s; s >>= 1) {
        if (t < s) red[t] += red[t + s];
        __syncthreads();
    }
    if (t == 0) out[b] = red[0];
}

// ---------------- launch ----------------
extern "C" void kernel_launch(void* const* d_in, const int* in_sizes, int n_in,
                              void* d_out, int out_size)
{
    (void)in_sizes; (void)n_in; (void)out_size;
    const int*   x       = (const int*)d_in[0];
    const int*   z       = (const int*)d_in[1];
    const float* lembs   = (const float*)d_in[2];
    const float* tlembs  = (const float*)d_in[3];
    const float* decW    = (const float*)d_in[4];
    const float* decb    = (const float*)d_in[5];
    const float* emW     = (const float*)d_in[6];
    const float* em_bias = (const float*)d_in[7];
    const float* em_g    = (const float*)d_in[8];
    const float* em_beta = (const float*)d_in[9];
    const float* tdW     = (const float*)d_in[10];
    const float* tdb     = (const float*)d_in[11];
    const float* tmW     = (const float*)d_in[12];
    const float* tm_bias = (const float*)d_in[13];
    const float* tn_g    = (const float*)d_in[14];
    const float* tn_beta = (const float*)d_in[15];
    float* out = (float*)d_out;

    cudaFuncSetAttribute(k_mlp_pre, cudaFuncAttributeMaxDynamicSharedMemorySize, SMEMSZ);
    cudaFuncSetAttribute(k_big, cudaFuncAttributeMaxDynamicSharedMemorySize, BIG_SMEM);

    // 1: query count (restores qcursor)
    k_qcount<<<NQ / 256, 256>>>(x, z);
    // 2: conversions + offsets (restores cnt/cur)
    k_cvt_offs<<<NQOFF + 1593, 256>>>(lembs, emW, tlembs, tmW, tdW, decW);
    // 3: MLPs + query fill
    k_mlp_pre<<<14 + NQ / 512, 512, SMEMSZ>>>(lembs, em_bias, em_g, em_beta,
                                              tm_bias, x, z);
    // 4: the big fused kernel (profiler slot)
    k_big<<<NRT + NVT, 512, BIG_SMEM>>>(tlembs, tn_g, tn_beta, tdb, decb);
    // 5-6: reductions
    k_red_em<<<K_, 128>>>();
    k_final<<<B_, 512>>>(z, out);
}